// round 1
// baseline (speedup 1.0000x reference)
#include <cuda_runtime.h>

// Problem constants
#define BB    32
#define CIN   64
#define HIN   128
#define WIN   128
#define COUT  128
#define OH    126
#define OW    126
#define NG    16
#define CPG   8        // channels per group
#define PH    63
#define PW    63
#define GN_EPS 1e-5f

// Scratch: conv output y [B, COUT, OH, OW]  (~260 MB) + group stats
__device__ float g_y[(size_t)BB * COUT * OH * OW];
__device__ float g_mean[BB * NG];
__device__ float g_rstd[BB * NG];

// ---------------------------------------------------------------------------
// Kernel 1: direct 3x3 conv (VALID) + bias -> g_y
// Block: 16 output channels x 16x16 pixel tile; thread: 1 channel, 4x4 pixels.
// ---------------------------------------------------------------------------
#define CO_T 16
#define CI_T 8
#define TILE 16

__global__ __launch_bounds__(256, 2)
void conv_kernel(const float* __restrict__ x,
                 const float* __restrict__ w,
                 const float* __restrict__ bias)
{
    __shared__ float xs[CI_T][18][18];     // input tile per ci-chunk
    __shared__ float ws[CO_T][CI_T][9];    // weights per (co, ci) chunk

    const int bx  = blockIdx.x;            // 8 tiles in x
    const int by  = blockIdx.y;            // 8 tiles in y
    const int bz  = blockIdx.z;            // b * 8 + co_tile
    const int b   = bz >> 3;
    const int co0 = (bz & 7) * CO_T;
    const int oy0 = by * TILE;
    const int ox0 = bx * TILE;

    const int tid  = threadIdx.x;
    const int co_l = tid >> 4;             // 0..15
    const int pos  = tid & 15;
    const int px0  = (pos & 3) * 4;
    const int py0  = (pos >> 2) * 4;

    float acc[16];
#pragma unroll
    for (int i = 0; i < 16; i++) acc[i] = 0.f;

    for (int ci0 = 0; ci0 < CIN; ci0 += CI_T) {
        // ---- load 18x18 input tile for CI_T channels ----
        for (int idx = tid; idx < CI_T * 18 * 18; idx += 256) {
            int cc  = idx / 324;
            int rem = idx - cc * 324;
            int r   = rem / 18;
            int c   = rem - r * 18;
            int gy  = oy0 + r;
            int gx  = ox0 + c;
            float v = 0.f;
            if (gy < HIN && gx < WIN)
                v = x[(((size_t)b * CIN + ci0 + cc) * HIN + gy) * WIN + gx];
            xs[cc][r][c] = v;
        }
        // ---- load weights ----
        for (int idx = tid; idx < CO_T * CI_T * 9; idx += 256) {
            int col = idx / 72;
            int rem = idx - col * 72;
            int cc  = rem / 9;
            int k   = rem - cc * 9;
            ws[col][cc][k] = w[((size_t)(co0 + col) * CIN + ci0 + cc) * 9 + k];
        }
        __syncthreads();

#pragma unroll
        for (int cc = 0; cc < CI_T; cc++) {
            float w9[9];
#pragma unroll
            for (int k = 0; k < 9; k++) w9[k] = ws[co_l][cc][k];

            float xr[6][6];
#pragma unroll
            for (int r = 0; r < 6; r++)
#pragma unroll
                for (int c = 0; c < 6; c++)
                    xr[r][c] = xs[cc][py0 + r][px0 + c];

#pragma unroll
            for (int iy = 0; iy < 4; iy++)
#pragma unroll
                for (int ix = 0; ix < 4; ix++) {
                    float s = acc[iy * 4 + ix];
                    s = fmaf(xr[iy    ][ix    ], w9[0], s);
                    s = fmaf(xr[iy    ][ix + 1], w9[1], s);
                    s = fmaf(xr[iy    ][ix + 2], w9[2], s);
                    s = fmaf(xr[iy + 1][ix    ], w9[3], s);
                    s = fmaf(xr[iy + 1][ix + 1], w9[4], s);
                    s = fmaf(xr[iy + 1][ix + 2], w9[5], s);
                    s = fmaf(xr[iy + 2][ix    ], w9[6], s);
                    s = fmaf(xr[iy + 2][ix + 1], w9[7], s);
                    s = fmaf(xr[iy + 2][ix + 2], w9[8], s);
                    acc[iy * 4 + ix] = s;
                }
        }
        __syncthreads();
    }

    const int   co = co0 + co_l;
    const float bv = bias[co];
#pragma unroll
    for (int iy = 0; iy < 4; iy++) {
        int oy = oy0 + py0 + iy;
        if (oy >= OH) continue;
#pragma unroll
        for (int ix = 0; ix < 4; ix++) {
            int ox = ox0 + px0 + ix;
            if (ox >= OW) continue;
            g_y[(((size_t)b * COUT + co) * OH + oy) * OW + ox] = acc[iy * 4 + ix] + bv;
        }
    }
}

// ---------------------------------------------------------------------------
// Kernel 2: per-(batch, group) mean / rstd over CPG*OH*OW contiguous floats.
// One block per (b, g); deterministic fixed-tree reduction.
// ---------------------------------------------------------------------------
__global__ __launch_bounds__(256)
void gn_stats_kernel()
{
    const int bg = blockIdx.x;                     // 0 .. B*NG-1
    const int N  = CPG * OH * OW;                  // 127008
    const float* __restrict__ p = g_y + (size_t)bg * N;

    const int tid = threadIdx.x;
    float s = 0.f, ss = 0.f;
    for (int i = tid; i < N; i += 256) {
        float v = p[i];
        s  += v;
        ss += v * v;
    }
    __shared__ float sh_s[256];
    __shared__ float sh_q[256];
    sh_s[tid] = s;
    sh_q[tid] = ss;
    __syncthreads();
    for (int off = 128; off > 0; off >>= 1) {
        if (tid < off) {
            sh_s[tid] += sh_s[tid + off];
            sh_q[tid] += sh_q[tid + off];
        }
        __syncthreads();
    }
    if (tid == 0) {
        float mean = sh_s[0] / (float)N;
        float var  = sh_q[0] / (float)N - mean * mean;
        g_mean[bg] = mean;
        g_rstd[bg] = rsqrtf(var + GN_EPS);
    }
}

// ---------------------------------------------------------------------------
// Kernel 3: normalize + affine + per-channel scale + 2x2 maxpool + clip [0,1]
// One thread per output element [B, COUT, 63, 63].
// ---------------------------------------------------------------------------
__global__ __launch_bounds__(256)
void fuse_out_kernel(const float* __restrict__ gw,
                     const float* __restrict__ gb,
                     const float* __restrict__ sc,
                     float* __restrict__ out)
{
    const int total = BB * COUT * PH * PW;
    int idx = blockIdx.x * blockDim.x + threadIdx.x;
    if (idx >= total) return;

    int px = idx % PW;
    int t  = idx / PW;
    int py = t % PH;  t /= PH;
    int c  = t % COUT;
    int b  = t / COUT;

    const int bg   = b * NG + (c >> 3);
    const float mean = g_mean[bg];
    const float rstd = g_rstd[bg];
    const float gwc  = gw[c];
    const float scc  = sc[c];
    const float a  = rstd * gwc * scc;
    const float bb = (gb[c] - mean * rstd * gwc) * scc;

    const float* yp = g_y + (((size_t)b * COUT + c) * OH + 2 * py) * OW + 2 * px;
    float v0 = fmaf(a, yp[0],      bb);
    float v1 = fmaf(a, yp[1],      bb);
    float v2 = fmaf(a, yp[OW],     bb);
    float v3 = fmaf(a, yp[OW + 1], bb);
    float m = fmaxf(fmaxf(v0, v1), fmaxf(v2, v3));
    out[idx] = fminf(fmaxf(m, 0.0f), 1.0f);
}

// ---------------------------------------------------------------------------
extern "C" void kernel_launch(void* const* d_in, const int* in_sizes, int n_in,
                              void* d_out, int out_size)
{
    const float* x      = (const float*)d_in[0];   // [32,64,128,128]
    const float* conv_w = (const float*)d_in[1];   // [128,64,3,3]
    const float* conv_b = (const float*)d_in[2];   // [128]
    const float* gn_w   = (const float*)d_in[3];   // [128]
    const float* gn_b   = (const float*)d_in[4];   // [128]
    const float* scale  = (const float*)d_in[5];   // [128,1,1]
    float* out = (float*)d_out;                    // [32,128,63,63]

    // Conv: grid (x-tiles, y-tiles, b * co-tiles)
    dim3 cgrid(8, 8, BB * (COUT / CO_T));
    conv_kernel<<<cgrid, 256>>>(x, conv_w, conv_b);

    // GroupNorm stats: one block per (b, group)
    gn_stats_kernel<<<BB * NG, 256>>>();

    // Fused epilogue
    const int total = BB * COUT * PH * PW;
    fuse_out_kernel<<<(total + 255) / 256, 256>>>(gn_w, gn_b, scale, out);
}

// round 2
// speedup vs baseline: 1.2400x; 1.2400x over previous
#include <cuda_runtime.h>

// Problem constants
#define BB    32
#define CIN   64
#define HIN   128
#define WIN   128
#define COUT  128
#define OH    126
#define OW    126
#define NG    16
#define CPG   8
#define PH    63
#define PW    63
#define GN_EPS 1e-5f

typedef unsigned long long u64;

__device__ float g_y[(size_t)BB * COUT * OH * OW];
__device__ float g_mean[BB * NG];
__device__ float g_rstd[BB * NG];

// ---- packed f32x2 helpers -------------------------------------------------
__device__ __forceinline__ u64 pack2(float lo, float hi) {
    u64 r;
    asm("mov.b64 %0, {%1, %2};" : "=l"(r) : "f"(lo), "f"(hi));
    return r;
}
__device__ __forceinline__ u64 ffma2(u64 a, u64 b, u64 c) {
    u64 d;
    asm("fma.rn.f32x2 %0, %1, %2, %3;" : "=l"(d) : "l"(a), "l"(b), "l"(c));
    return d;
}
__device__ __forceinline__ void unpack2(u64 v, float& lo, float& hi) {
    asm("mov.b64 {%0, %1}, %2;" : "=f"(lo), "=f"(hi) : "l"(v));
}

// ---------------------------------------------------------------------------
// Kernel 1: direct 3x3 conv (VALID) + bias -> g_y
// Block: 16 output channels x 16x16 pixel tile; thread: 1 channel, 4x4 pixels.
// Packed FFMA2 over horizontal output pairs; vectorized smem loads.
// ---------------------------------------------------------------------------
#define CO_T 16
#define CI_T 8
#define TILE 16
#define XROW 20   // padded row (floats) -> 80B, 16B-aligned rows

__global__ __launch_bounds__(256, 3)
void conv_kernel(const float* __restrict__ x,
                 const float* __restrict__ w,
                 const float* __restrict__ bias)
{
    __shared__ __align__(16) float  xs[CI_T][18][XROW];
    __shared__ __align__(16) float2 ws2[CO_T][CI_T][9];   // duplicated weight pairs

    const int bx  = blockIdx.x;            // 8 tiles in x
    const int by  = blockIdx.y;            // 8 tiles in y
    const int bz  = blockIdx.z;            // b * 8 + co_tile
    const int b   = bz >> 3;
    const int co0 = (bz & 7) * CO_T;
    const int oy0 = by * TILE;
    const int ox0 = bx * TILE;

    const int tid  = threadIdx.x;
    const int co_l = tid >> 4;             // 0..15
    const int pos  = tid & 15;
    const int px0  = (pos & 3) * 4;
    const int py0  = (pos >> 2) * 4;

    u64 acc2[4][2];                        // [iy][half], half0 = ix{0,1}, half1 = ix{2,3}
    const u64 z2 = pack2(0.f, 0.f);
#pragma unroll
    for (int i = 0; i < 4; i++) { acc2[i][0] = z2; acc2[i][1] = z2; }

    for (int ci0 = 0; ci0 < CIN; ci0 += CI_T) {
        // ---- load 18x18 input tile for CI_T channels ----
        for (int idx = tid; idx < CI_T * 18 * 18; idx += 256) {
            int cc  = idx / 324;
            int rem = idx - cc * 324;
            int r   = rem / 18;
            int c   = rem - r * 18;
            int gy  = oy0 + r;
            int gx  = ox0 + c;
            float v = 0.f;
            if (gy < HIN && gx < WIN)
                v = x[(((size_t)b * CIN + ci0 + cc) * HIN + gy) * WIN + gx];
            xs[cc][r][c] = v;
        }
        // ---- load weights, duplicated into float2 pairs ----
        for (int idx = tid; idx < CO_T * CI_T * 9; idx += 256) {
            int col = idx / 72;
            int rem = idx - col * 72;
            int cc  = rem / 9;
            int k   = rem - cc * 9;
            float wv = w[((size_t)(co0 + col) * CIN + ci0 + cc) * 9 + k];
            ws2[col][cc][k] = make_float2(wv, wv);
        }
        __syncthreads();

#pragma unroll
        for (int cc = 0; cc < CI_T; cc++) {
            u64 wp[9];
#pragma unroll
            for (int k = 0; k < 9; k++)
                wp[k] = *reinterpret_cast<const u64*>(&ws2[co_l][cc][k]);  // LDS.64 broadcast

#pragma unroll
            for (int r = 0; r < 6; r++) {
                const float4 f = *reinterpret_cast<const float4*>(&xs[cc][py0 + r][px0]);
                const float2 g = *reinterpret_cast<const float2*>(&xs[cc][py0 + r][px0 + 4]);
                const u64 p01 = pack2(f.x, f.y);
                const u64 p12 = pack2(f.y, f.z);
                const u64 p23 = pack2(f.z, f.w);
                const u64 p34 = pack2(f.w, g.x);
                const u64 p45 = pack2(g.x, g.y);
#pragma unroll
                for (int iy = 0; iy < 4; iy++) {
                    const int kr = r - iy;         // kernel row; valid 0..2
                    if (kr < 0 || kr > 2) continue;
                    acc2[iy][0] = ffma2(p01, wp[kr * 3 + 0], acc2[iy][0]);
                    acc2[iy][0] = ffma2(p12, wp[kr * 3 + 1], acc2[iy][0]);
                    acc2[iy][0] = ffma2(p23, wp[kr * 3 + 2], acc2[iy][0]);
                    acc2[iy][1] = ffma2(p23, wp[kr * 3 + 0], acc2[iy][1]);
                    acc2[iy][1] = ffma2(p34, wp[kr * 3 + 1], acc2[iy][1]);
                    acc2[iy][1] = ffma2(p45, wp[kr * 3 + 2], acc2[iy][1]);
                }
            }
        }
        __syncthreads();
    }

    const int   co = co0 + co_l;
    const float bv = bias[co];
#pragma unroll
    for (int iy = 0; iy < 4; iy++) {
        int oy = oy0 + py0 + iy;
        if (oy >= OH) continue;
        float v0, v1, v2, v3;
        unpack2(acc2[iy][0], v0, v1);
        unpack2(acc2[iy][1], v2, v3);
        float vals[4] = {v0, v1, v2, v3};
        float* yp = &g_y[(((size_t)b * COUT + co) * OH + oy) * OW + ox0 + px0];
#pragma unroll
        for (int ix = 0; ix < 4; ix++) {
            int ox = ox0 + px0 + ix;
            if (ox < OW) yp[ix] = vals[ix] + bv;
        }
    }
}

// ---------------------------------------------------------------------------
// Kernel 2: per-(batch, group) mean / rstd, float4 vectorized, fixed tree.
// ---------------------------------------------------------------------------
__global__ __launch_bounds__(256)
void gn_stats_kernel()
{
    const int bg = blockIdx.x;                     // 0 .. B*NG-1
    const int N  = CPG * OH * OW;                  // 127008 (mult of 4)
    const float4* __restrict__ p4 =
        reinterpret_cast<const float4*>(g_y + (size_t)bg * N);
    const int N4 = N / 4;

    const int tid = threadIdx.x;
    float s = 0.f, ss = 0.f;
    for (int i = tid; i < N4; i += 256) {
        float4 v = p4[i];
        s  += v.x + v.y + v.z + v.w;
        ss += v.x * v.x + v.y * v.y + v.z * v.z + v.w * v.w;
    }
    __shared__ float sh_s[256];
    __shared__ float sh_q[256];
    sh_s[tid] = s;
    sh_q[tid] = ss;
    __syncthreads();
    for (int off = 128; off > 0; off >>= 1) {
        if (tid < off) {
            sh_s[tid] += sh_s[tid + off];
            sh_q[tid] += sh_q[tid + off];
        }
        __syncthreads();
    }
    if (tid == 0) {
        float mean = sh_s[0] / (float)N;
        float var  = sh_q[0] / (float)N - mean * mean;
        g_mean[bg] = mean;
        g_rstd[bg] = rsqrtf(var + GN_EPS);
    }
}

// ---------------------------------------------------------------------------
// Kernel 3: normalize + affine + scale + 2x2 maxpool + clip [0,1]
// ---------------------------------------------------------------------------
__global__ __launch_bounds__(256)
void fuse_out_kernel(const float* __restrict__ gw,
                     const float* __restrict__ gb,
                     const float* __restrict__ sc,
                     float* __restrict__ out)
{
    const int total = BB * COUT * PH * PW;
    int idx = blockIdx.x * blockDim.x + threadIdx.x;
    if (idx >= total) return;

    int px = idx % PW;
    int t  = idx / PW;
    int py = t % PH;  t /= PH;
    int c  = t % COUT;
    int b  = t / COUT;

    const int bg     = b * NG + (c >> 3);
    const float mean = g_mean[bg];
    const float rstd = g_rstd[bg];
    const float gwc  = gw[c];
    const float scc  = sc[c];
    const float a    = rstd * gwc * scc;
    const float bb   = (gb[c] - mean * rstd * gwc) * scc;

    const float* yp = g_y + (((size_t)b * COUT + c) * OH + 2 * py) * OW + 2 * px;
    float v0 = fmaf(a, yp[0],      bb);
    float v1 = fmaf(a, yp[1],      bb);
    float v2 = fmaf(a, yp[OW],     bb);
    float v3 = fmaf(a, yp[OW + 1], bb);
    float m = fmaxf(fmaxf(v0, v1), fmaxf(v2, v3));
    out[idx] = fminf(fmaxf(m, 0.0f), 1.0f);
}

// ---------------------------------------------------------------------------
extern "C" void kernel_launch(void* const* d_in, const int* in_sizes, int n_in,
                              void* d_out, int out_size)
{
    const float* x      = (const float*)d_in[0];   // [32,64,128,128]
    const float* conv_w = (const float*)d_in[1];   // [128,64,3,3]
    const float* conv_b = (const float*)d_in[2];   // [128]
    const float* gn_w   = (const float*)d_in[3];   // [128]
    const float* gn_b   = (const float*)d_in[4];   // [128]
    const float* scale  = (const float*)d_in[5];   // [128,1,1]
    float* out = (float*)d_out;                    // [32,128,63,63]

    dim3 cgrid(8, 8, BB * (COUT / CO_T));
    conv_kernel<<<cgrid, 256>>>(x, conv_w, conv_b);

    gn_stats_kernel<<<BB * NG, 256>>>();

    const int total = BB * COUT * PH * PW;
    fuse_out_kernel<<<(total + 255) / 256, 256>>>(gn_w, gn_b, scale, out);
}